// round 12
// baseline (speedup 1.0000x reference)
#include <cuda_runtime.h>
#include <cuda_fp16.h>
#include <cstdint>

#define UQ   2048
#define BB   4
#define DD   512
#define QL   2176
#define KVL  2176
#define NH   8
#define DH   64
#define NEGINF (-100000000.0f)
#define MROWS (QL*BB)          // 8704
#define RCU_ROWS 2112
#define RCU_SZ (2112*4*512)
#define NWORD 34               // KVL/64
#define NITEMS (BB * NH * (QL / 128))   // 544 attention work items
#define QSCALE (0.125f * 1.44269504088896f)   // dh^-0.5 * log2(e)

// -------------------- device scratch ----------------------------------------
__device__ __half g_qin16 [MROWS * DD];
__device__ __half g_kvin16[MROWS * DD];
__device__ __half g_q16   [MROWS * DD];
__device__ __half g_k16   [MROWS * DD];
__device__ __half g_v16   [MROWS * DD];   // plain [token*BB+b][dh] (same as K)
__device__ __half g_attn16[MROWS * DD];
__device__ __half g_wqt [512 * 512];
__device__ __half g_wkvt[1024 * 512];
__device__ __half g_wot [512 * 512];
__device__ unsigned long long g_mbits[BB * QL * NWORD];
__device__ int g_flags[3];    // static-zero; monotone atomicOr (replay-stable)
__device__ int g_perm[BB];    // batches sorted by length desc (LPT)
__device__ int g_ticket;      // work-stealing counter (reset in prep_convert)

// -------------------- helpers ------------------------------------------------
__device__ __forceinline__ void hmma(float* c,
    uint32_t a0, uint32_t a1, uint32_t a2, uint32_t a3,
    uint32_t b0, uint32_t b1) {
    asm volatile(
        "mma.sync.aligned.m16n8k16.row.col.f32.f16.f16.f32 "
        "{%0,%1,%2,%3}, {%4,%5,%6,%7}, {%8,%9}, {%0,%1,%2,%3};\n"
        : "+f"(c[0]), "+f"(c[1]), "+f"(c[2]), "+f"(c[3])
        : "r"(a0), "r"(a1), "r"(a2), "r"(a3), "r"(b0), "r"(b1));
}
__device__ __forceinline__ void ldsm4(uint32_t& r0, uint32_t& r1,
                                      uint32_t& r2, uint32_t& r3, uint32_t a) {
    asm volatile("ldmatrix.sync.aligned.m8n8.x4.shared.b16 {%0,%1,%2,%3}, [%4];"
        : "=r"(r0), "=r"(r1), "=r"(r2), "=r"(r3) : "r"(a));
}
__device__ __forceinline__ void ldsm4t(uint32_t& r0, uint32_t& r1,
                                       uint32_t& r2, uint32_t& r3, uint32_t a) {
    asm volatile("ldmatrix.sync.aligned.m8n8.x4.trans.shared.b16 {%0,%1,%2,%3}, [%4];"
        : "=r"(r0), "=r"(r1), "=r"(r2), "=r"(r3) : "r"(a));
}
__device__ __forceinline__ uint32_t packh2(float lo, float hi) {
    uint32_t r; asm("cvt.rn.f16x2.f32 %0, %1, %2;" : "=r"(r) : "f"(hi), "f"(lo));
    return r;
}
__device__ __forceinline__ float ex2(float x) {
    float r; asm("ex2.approx.f32 %0, %1;" : "=f"(r) : "f"(x)); return r;
}
__device__ __forceinline__ uint32_t s2u(const void* p) {
    return (uint32_t)__cvta_generic_to_shared(p);
}
#define CP16(dst, src) \
    asm volatile("cp.async.cg.shared.global [%0], [%1], 16;\n" :: "r"(dst), "l"(src))
#define CP_COMMIT() asm volatile("cp.async.commit_group;\n")

// -------------------- fused prep: gather/convert + mask sniff + LPT perm -----
__global__ void prep_convert(const float* __restrict__ utt,
                             const float* __restrict__ rc,
                             const float* __restrict__ summ,
                             const float* __restrict__ mem,
                             const unsigned char* __restrict__ rawmask,
                             const int* __restrict__ lengths) {
    const int QN = MROWS * 128;
    int bid = blockIdx.x;
    if (bid < 8704) {
        int i = bid * blockDim.x + threadIdx.x;
        if (i < QN) {
            int row = i >> 7;
            float4 v;
            if (row < 256)       v = ((const float4*)rc)[i];
            else if (row < 8448) v = ((const float4*)utt)[i - 256 * 128];
            else                 v = ((const float4*)summ)[i - 8448 * 128];
            uint2 o; o.x = packh2(v.x, v.y); o.y = packh2(v.z, v.w);
            ((uint2*)g_qin16)[i] = o;
        } else {
            int j = i - QN;
            int row = j >> 7;
            float4 v;
            if (row < 256)      v = ((const float4*)mem)[j];
            else if (row < 512) v = ((const float4*)rc)[j - 256 * 128];
            else                v = ((const float4*)utt)[j - 512 * 128];
            uint2 o; o.x = packh2(v.x, v.y); o.y = packh2(v.z, v.w);
            ((uint2*)g_kvin16)[j] = o;
        }
    } else {
        int sb = bid - 8704;
        int f0 = 0, f1 = 0, f2 = 0;
        const int SCAN = 1 << 20;
        int stride = 64 * blockDim.x * 4;
        for (int i = (sb * blockDim.x + threadIdx.x) * 4; i < SCAN; i += stride) {
            uchar4 v = *(const uchar4*)(rawmask + i);
            if (v.x > 1 || v.y > 1) f0 = 1;
            if (v.z > 1 || v.w > 1) f1 = 1;
            if (v.y | v.z | v.w)    f2 = 1;
        }
        if (f0) atomicOr(&g_flags[0], 1);
        if (f1) atomicOr(&g_flags[1], 1);
        if (f2) atomicOr(&g_flags[2], 1);
        if (sb == 0 && threadIdx.x == 0) {
            g_ticket = 0;   // reset work-stealing counter every launch/replay
            int len[BB], idx[BB];
            for (int i = 0; i < BB; i++) { len[i] = __ldg(lengths + i); idx[i] = i; }
            for (int i = 1; i < BB; i++) {
                int l = len[i], ix = idx[i], j = i - 1;
                while (j >= 0 && len[j] < l) {
                    len[j + 1] = len[j]; idx[j + 1] = idx[j]; j--;
                }
                len[j + 1] = l; idx[j + 1] = ix;
            }
            for (int i = 0; i < BB; i++) g_perm[i] = idx[i];
        }
    }
}

// -------------------- fused weight transpose + mask pack ----------------------
__global__ void wconv_pack(const float* __restrict__ wq,
                           const float* __restrict__ wkv,
                           const float* __restrict__ wo,
                           const void* __restrict__ raw,
                           const int* __restrict__ lengths) {
    int bid = blockIdx.x;
    if (bid < 1024) {
        __shared__ float tile[32][33];
        const float* W; __half* Wt; int NN, bx, by;
        if (bid < 256)      { W = wq;  Wt = g_wqt;  NN = 512;  bx = bid & 15; by = bid >> 4; }
        else if (bid < 768) { int b2 = bid - 256; W = wkv; Wt = g_wkvt; NN = 1024; bx = b2 & 31; by = b2 >> 5; }
        else                { int b2 = bid - 768; W = wo;  Wt = g_wot;  NN = 512;  bx = b2 & 15; by = b2 >> 4; }
        int x = threadIdx.x & 31, y0 = threadIdx.x >> 5;
        #pragma unroll
        for (int yy = y0; yy < 32; yy += 8)
            tile[yy][x] = W[(size_t)(by * 32 + yy) * NN + bx * 32 + x];
        __syncthreads();
        #pragma unroll
        for (int yy = y0; yy < 32; yy += 8)
            Wt[(size_t)(bx * 32 + yy) * 512 + by * 32 + x] =
                __float2half_rn(tile[x][yy]);
        return;
    }
    // ---- mask pack: one warp per (q, word) ----
    int warp = ((bid - 1024) * blockDim.x + threadIdx.x) >> 5;
    int lane = threadIdx.x & 31;
    if (warp >= QL * NWORD) return;
    int q = warp / NWORD, w = warp - q * NWORD;

    int kind;
    if (g_flags[0])      kind = 3;
    else if (g_flags[1]) kind = 2;
    else if (g_flags[2]) kind = 0;
    else                 kind = 1;

    size_t base = (size_t)q * KVL + w * 64;
    bool m0, m1;
    if (kind == 0) {
        const unsigned char* p = (const unsigned char*)raw;
        m0 = p[base + lane] != 0; m1 = p[base + 32 + lane] != 0;
    } else if (kind == 1) {
        const int* p = (const int*)raw;
        m0 = p[base + lane] != 0; m1 = p[base + 32 + lane] != 0;
    } else if (kind == 2) {
        const float* p = (const float*)raw;
        m0 = p[base + lane] != 0.f; m1 = p[base + 32 + lane] != 0.f;
    } else {
        const unsigned short* p = (const unsigned short*)raw;
        m0 = (p[base + lane] & 0x7fff) != 0;
        m1 = (p[base + 32 + lane] & 0x7fff) != 0;
    }
    uint32_t lo = __ballot_sync(0xffffffffu, m0);
    uint32_t hi = __ballot_sync(0xffffffffu, m1);
    unsigned long long word = (unsigned long long)lo |
                              ((unsigned long long)hi << 32);
    if (lane < 4) {
        int limit = 128 + __ldg(lengths + lane);
        int k0 = w * 64;
        unsigned long long pad;
        if (limit <= k0)           pad = ~0ull;
        else if (limit >= k0 + 64) pad = 0ull;
        else                       pad = (~0ull) << (limit - k0);
        g_mbits[((size_t)lane * QL + q) * NWORD + w] = word | pad;
    }
}

// -------------------- fp16 GEMM core (ldmatrix fragments) --------------------
struct GemmAcc { float a[2][8][4]; };

__device__ __forceinline__ void gemm_main(uint32_t* sm, const __half* A,
                                          const __half* Wt, int m0, int n0,
                                          GemmAcc& acc) {
    const int tid = threadIdx.x;
    const int wid = tid >> 5, lane = tid & 31;
    const int qq = lane >> 3, rr = lane & 7;
    const int wm = wid & 3, wn = wid >> 2;

    const uint32_t a_off = (uint32_t)((((qq & 1) << 3) + rr) * 36 + ((qq >> 1) << 2));
    const uint32_t b_off = (uint32_t)(((wn * 64) + ((qq >> 1) << 3) + rr) * 36 + ((qq & 1) << 2));

    #pragma unroll
    for (int mf = 0; mf < 2; mf++)
        #pragma unroll
        for (int nf = 0; nf < 8; nf++)
            #pragma unroll
            for (int e = 0; e < 4; e++) acc.a[mf][nf][e] = 0.f;

    auto issue = [&](int t) {
        int k0 = t * 64;
        uint32_t* As = sm + (t & 1) * 4608;
        uint32_t* Bs = sm + 9216 + (t & 1) * 4608;
        #pragma unroll
        for (int l = 0; l < 4; l++) {
            int item = tid + l * 256;
            int row = item >> 3, c = item & 7;
            CP16(s2u(As + row * 36 + c * 4),
                 A + (size_t)(m0 + row) * 512 + k0 + c * 8);
        }
        #pragma unroll
        for (int l = 0; l < 4; l++) {
            int item = tid + l * 256;
            int row = item >> 3, c = item & 7;
            CP16(s2u(Bs + row * 36 + c * 4),
                 Wt + (size_t)(n0 + row) * 512 + k0 + c * 8);
        }
        CP_COMMIT();
    };

    issue(0);
    #pragma unroll 1
    for (int t = 0; t < 8; t++) {
        if (t + 1 < 8) {
            issue(t + 1);
            asm volatile("cp.async.wait_group 1;\n");
        } else {
            asm volatile("cp.async.wait_group 0;\n");
        }
        __syncthreads();
        uint32_t as_base = s2u(sm + (t & 1) * 4608) + a_off * 4;
        uint32_t bs_base = s2u(sm + 9216 + (t & 1) * 4608) + b_off * 4;
        #pragma unroll
        for (int kc = 0; kc < 4; kc++) {
            uint32_t a[2][4];
            #pragma unroll
            for (int mf = 0; mf < 2; mf++)
                ldsm4(a[mf][0], a[mf][1], a[mf][2], a[mf][3],
                      as_base + (uint32_t)(((wm * 32 + mf * 16) * 36 + kc * 8) * 4));
            #pragma unroll
            for (int P = 0; P < 4; P++) {
                uint32_t b0, b1, b2, b3;
                ldsm4(b0, b1, b2, b3,
                      bs_base + (uint32_t)((P * 16 * 36 + kc * 8) * 4));
                hmma(acc.a[0][2 * P],     a[0][0], a[0][1], a[0][2], a[0][3], b0, b1);
                hmma(acc.a[1][2 * P],     a[1][0], a[1][1], a[1][2], a[1][3], b0, b1);
                hmma(acc.a[0][2 * P + 1], a[0][0], a[0][1], a[0][2], a[0][3], b2, b3);
                hmma(acc.a[1][2 * P + 1], a[1][0], a[1][1], a[1][2], a[1][3], b2, b3);
            }
        }
        __syncthreads();
    }
}

// -------------------- merged Q + KV projection -------------------------------
__global__ __launch_bounds__(256, 2)
void qkv_gemm(const __half* __restrict__ qA, const __half* __restrict__ kvA,
              const __half* __restrict__ wq, const __half* __restrict__ wkv,
              const float* __restrict__ bq, const float* __restrict__ bkv) {
    extern __shared__ uint32_t sm[];
    const bool isQ = blockIdx.x < 4;
    const int n0 = isQ ? blockIdx.x * 128 : (blockIdx.x - 4) * 128;
    const int m0 = blockIdx.y * 128;
    const __half* A  = isQ ? qA : kvA;
    const __half* Wt = isQ ? wq : wkv;
    const float* bias = isQ ? bq : bkv;

    GemmAcc acc;
    gemm_main(sm, A, Wt, m0, n0, acc);

    const int lane = threadIdx.x & 31, wid = threadIdx.x >> 5;
    const int g = lane >> 2, tig = lane & 3;
    const int wm = wid & 3, wn = wid >> 2;
    #pragma unroll
    for (int mf = 0; mf < 2; mf++) {
        int row0 = m0 + wm * 32 + mf * 16 + g;
        int row1 = row0 + 8;
        #pragma unroll
        for (int nf = 0; nf < 8; nf++) {
            int col = n0 + wn * 64 + nf * 8 + 2 * tig;
            float bi0 = __ldg(bias + col), bi1 = __ldg(bias + col + 1);
            float v00 = acc.a[mf][nf][0] + bi0, v01 = acc.a[mf][nf][1] + bi1;
            float v10 = acc.a[mf][nf][2] + bi0, v11 = acc.a[mf][nf][3] + bi1;
            if (isQ) {
                *(__half2*)(&g_q16[(size_t)row0 * DD + col]) =
                    __floats2half2_rn(v00 * QSCALE, v01 * QSCALE);
                *(__half2*)(&g_q16[(size_t)row1 * DD + col]) =
                    __floats2half2_rn(v10 * QSCALE, v11 * QSCALE);
            } else {
                __half* dst = (col < 512) ? g_k16 : g_v16;
                int c = (col < 512) ? col : col - 512;
                *(__half2*)(&dst[(size_t)row0 * DD + c]) = __floats2half2_rn(v00, v01);
                *(__half2*)(&dst[(size_t)row1 * DD + c]) = __floats2half2_rn(v10, v11);
            }
        }
    }
}

// -------------------- output projection (slice/clip scatter) -----------------
__global__ __launch_bounds__(256, 2)
void out_gemm(const __half* __restrict__ A, const __half* __restrict__ Wt,
              const float* __restrict__ bias, float* __restrict__ C) {
    extern __shared__ uint32_t sm[];
    const int m0 = blockIdx.y * 128, n0 = blockIdx.x * 128;
    GemmAcc acc;
    gemm_main(sm, A, Wt, m0, n0, acc);

    const int lane = threadIdx.x & 31, wid = threadIdx.x >> 5;
    const int g = lane >> 2, tig = lane & 3;
    const int wm = wid & 3, wn = wid >> 2;
    #pragma unroll
    for (int mf = 0; mf < 2; mf++) {
        int row0 = m0 + wm * 32 + mf * 16 + g;
        #pragma unroll
        for (int nf = 0; nf < 8; nf++) {
            int col = n0 + wn * 64 + nf * 8 + 2 * tig;
            float bi0 = __ldg(bias + col), bi1 = __ldg(bias + col + 1);
            float vs[2][2] = {
                {acc.a[mf][nf][0] + bi0, acc.a[mf][nf][1] + bi1},
                {acc.a[mf][nf][2] + bi0, acc.a[mf][nf][3] + bi1}};
            #pragma unroll
            for (int r = 0; r < 2; r++) {
                int m = row0 + r * 8;
                int q = m >> 2, b = m & 3;
                if (q < RCU_ROWS) {
                    *(float2*)(C + (size_t)m * DD + col) =
                        make_float2(vs[r][0], vs[r][1]);
                } else if (q < QL - 1) {
                    float a0 = fminf(fmaxf(vs[r][0], -10.f), 10.f);
                    float a1 = fminf(fmaxf(vs[r][1], -10.f), 10.f);
                    *(float2*)(C + RCU_SZ +
                        (size_t)((q - RCU_ROWS) * BB + b) * DD + col) =
                        make_float2(a0, a1);
                }
            }
        }
    }
}

// -------------------- persistent fp16 flash attention (work stealing) ---------
// 296 persistent CTAs pull (b,h,q-tile) items off a global ticket in LPT order.
// Max-free softmax (p = 2^s), 3-stage cp.async pipeline, bit-packed masks.
__global__ __launch_bounds__(256, 2)
void attn_h16(const int* __restrict__ lengths) {
    extern __shared__ uint32_t sm[];
    __shared__ int s_item;
    uint32_t* Qs = sm;

    const int tid = threadIdx.x;
    const int wid = tid >> 5, lane = tid & 31;
    const int g = lane >> 2, tig = lane & 3;
    const int qq = lane >> 3, rr = lane & 7;
    const int wrow = wid * 16;

    const uint32_t qa_off = (uint32_t)((wrow + ((qq & 1) << 3) + rr) * 36 + ((qq >> 1) << 2));
    const uint32_t kb_off = (uint32_t)((((qq >> 1) << 3) + rr) * 36 + ((qq & 1) << 2));
    const uint32_t vb_off = (uint32_t)((((qq & 1) << 3) + rr) * 36 + ((qq >> 1) << 2));
    const uint32_t qa_base = s2u(Qs) + qa_off * 4;

    for (;;) {
        if (tid == 0) s_item = atomicAdd(&g_ticket, 1);
        __syncthreads();
        int item = s_item;
        if (item >= NITEMS) break;

        // LPT decode: longest batches first (136 items per batch)
        const int b = g_perm[item / 136];
        int rem = item - (item / 136) * 136;
        const int h = rem / 17;
        const int q0 = (rem - h * 17) * 128;

        const int qg0 = q0 + wrow + g;
        const int qg1 = qg0 + 8;
        const unsigned long long* mrow0 = g_mbits + ((size_t)b * QL + qg0) * NWORD;
        const unsigned long long* mrow1 = g_mbits + ((size_t)b * QL + qg1) * NWORD;
        const int limit = 128 + __ldg(lengths + b);
        const int NTb = min(NWORD, (limit + 63) >> 6);

        auto load_kv = [&](int t, uint32_t* stage) {
            int k0 = t * 64;
            uint32_t* Ks = stage;
            uint32_t* Vs = stage + 2304;
            #pragma unroll
            for (int l = 0; l < 2; l++) {
                int it2 = tid + l * 256;
                int row = it2 >> 3, c = it2 & 7;
                CP16(s2u(Ks + row * 36 + c * 4),
                     g_k16 + ((size_t)(k0 + row) * BB + b) * DD + h * DH + c * 8);
            }
            #pragma unroll
            for (int l = 0; l < 2; l++) {
                int it2 = tid + l * 256;
                int row = it2 >> 3, c = it2 & 7;
                CP16(s2u(Vs + row * 36 + c * 4),
                     g_v16 + ((size_t)(k0 + row) * BB + b) * DD + h * DH + c * 8);
            }
        };

        #pragma unroll
        for (int l = 0; l < 4; l++) {
            int it2 = tid + l * 256;
            int row = it2 >> 3, c = it2 & 7;
            CP16(s2u(Qs + row * 36 + c * 4),
                 g_q16 + ((size_t)(q0 + row) * BB + b) * DD + h * DH + c * 8);
        }
        load_kv(0, sm + 4608);
        CP_COMMIT();
        if (1 < NTb) load_kv(1, sm + 4608 + 4608);
        CP_COMMIT();

        float l0 = 0.f, l1 = 0.f;
        float o[8][4];
        #pragma unroll
        for (int nf = 0; nf < 8; nf++)
            #pragma unroll
            for (int e = 0; e < 4; e++) o[nf][e] = 0.f;

        int st = 0, st2 = 2;
        #pragma unroll 1
        for (int t = 0; t < NTb; t++) {
            unsigned long long w0 = mrow0[t], w1 = mrow1[t];

            if (t + 2 < NTb) load_kv(t + 2, sm + 4608 + st2 * 4608);
            CP_COMMIT();
            asm volatile("cp.async.wait_group 2;\n");
            __syncthreads();

            uint32_t* stage = sm + 4608 + st * 4608;
            const uint32_t ks_base = s2u(stage) + kb_off * 4;
            const uint32_t vs_base = s2u(stage + 2304) + vb_off * 4;

            // S = Q @ K^T
            float s[8][4];
            #pragma unroll
            for (int nf = 0; nf < 8; nf++)
                #pragma unroll
                for (int e = 0; e < 4; e++) s[nf][e] = 0.f;
            #pragma unroll
            for (int kc = 0; kc < 4; kc++) {
                uint32_t a0, a1, a2, a3;
                ldsm4(a0, a1, a2, a3, qa_base + (uint32_t)(kc * 32));
                #pragma unroll
                for (int P = 0; P < 4; P++) {
                    uint32_t b0, b1, b2, b3;
                    ldsm4(b0, b1, b2, b3,
                          ks_base + (uint32_t)((P * 16 * 36 + kc * 8) * 4));
                    hmma(s[2 * P],     a0, a1, a2, a3, b0, b1);
                    hmma(s[2 * P + 1], a0, a1, a2, a3, b2, b3);
                }
            }

            // mask -> p = 2^s -> accumulate l (no max, no reductions)
            #pragma unroll
            for (int nf = 0; nf < 8; nf++) {
                int sh = nf * 8 + 2 * tig;
                uint32_t b0 = (uint32_t)(w0 >> sh);
                uint32_t b1 = (uint32_t)(w1 >> sh);
                if (b0 & 1) s[nf][0] = NEGINF;
                if (b0 & 2) s[nf][1] = NEGINF;
                if (b1 & 1) s[nf][2] = NEGINF;
                if (b1 & 2) s[nf][3] = NEGINF;
                s[nf][0] = ex2(s[nf][0]);
                s[nf][1] = ex2(s[nf][1]);
                s[nf][2] = ex2(s[nf][2]);
                s[nf][3] = ex2(s[nf][3]);
                l0 += s[nf][0] + s[nf][1];
                l1 += s[nf][2] + s[nf][3];
            }

            // O += P @ V (V via ldmatrix.trans)
            #pragma unroll
            for (int kc = 0; kc < 4; kc++) {
                uint32_t pa0 = packh2(s[2 * kc][0],     s[2 * kc][1]);
                uint32_t pa1 = packh2(s[2 * kc][2],     s[2 * kc][3]);
                uint32_t pa2 = packh2(s[2 * kc + 1][0], s[2 * kc + 1][1]);
                uint32_t pa3 = packh2(s[2 * kc + 1][2], s[2 * kc + 1][3]);
                #pragma unroll
                for (int P = 0; P < 4; P++) {
                    uint32_t b0, b1, b2, b3;
                    ldsm4t(b0, b1, b2, b3,
                           vs_base + (uint32_t)((kc * 16 * 36 + P * 8) * 4));
                    hmma(o[2 * P],     pa0, pa1, pa2, pa3, b0, b1);
                    hmma(o[2 * P + 1], pa0, pa1, pa2, pa3, b2, b3);
                }
            }
            __syncthreads();

            st  = (st  == 2) ? 0 : st + 1;
            st2 = (st2 == 2) ? 0 : st2 + 1;
        }

        // final cross-lane reduction of l per row
        l0 += __shfl_xor_sync(0xffffffffu, l0, 1);
        l0 += __shfl_xor_sync(0xffffffffu, l0, 2);
        l1 += __shfl_xor_sync(0xffffffffu, l1, 1);
        l1 += __shfl_xor_sync(0xffffffffu, l1, 2);
        float inv0 = 1.0f / l0, inv1 = 1.0f / l1;
        #pragma unroll
        for (int nf = 0; nf < 8; nf++) {
            int col = h * DH + nf * 8 + 2 * tig;
            *(__half2*)(&g_attn16[((size_t)qg0 * BB + b) * DD + col]) =
                __floats2half2_rn(o[nf][0] * inv0, o[nf][1] * inv0);
            *(__half2*)(&g_attn16[((size_t)qg1 * BB + b) * DD + col]) =
                __floats2half2_rn(o[nf][2] * inv1, o[nf][3] * inv1);
        }
        // loop: broadcast sync at top guarantees smem reuse is safe
    }
}

// -------------------- launch ------------------------------------------------
extern "C" void kernel_launch(void* const* d_in, const int* in_sizes, int n_in,
                              void* d_out, int out_size) {
    const float* utt      = (const float*)d_in[0];
    const int*   lengths  = (const int*)d_in[1];
    const float* rc       = (const float*)d_in[2];
    const float* summ     = (const float*)d_in[3];
    const float* mem      = (const float*)d_in[4];
    const void*  mask_raw = (const void*)d_in[5];
    const float* w_q   = (const float*)d_in[6];
    const float* b_q   = (const float*)d_in[7];
    const float* w_kv  = (const float*)d_in[8];
    const float* b_kv  = (const float*)d_in[9];
    const float* w_out = (const float*)d_in[10];
    const float* b_out = (const float*)d_in[11];
    float* out = (float*)d_out;

    void *p;
    cudaGetSymbolAddress(&p, g_qin16);  __half* qin16  = (__half*)p;
    cudaGetSymbolAddress(&p, g_kvin16); __half* kvin16 = (__half*)p;
    cudaGetSymbolAddress(&p, g_attn16); __half* attn16 = (__half*)p;
    cudaGetSymbolAddress(&p, g_wqt);    __half* wqt    = (__half*)p;
    cudaGetSymbolAddress(&p, g_wkvt);   __half* wkvt   = (__half*)p;
    cudaGetSymbolAddress(&p, g_wot);    __half* wot    = (__half*)p;

    const int GSM = 18432 * 4;
    cudaFuncSetAttribute(qkv_gemm,
                         cudaFuncAttributeMaxDynamicSharedMemorySize, GSM);
    cudaFuncSetAttribute(out_gemm,
                         cudaFuncAttributeMaxDynamicSharedMemorySize, GSM);
    const int ASM = 18432 * 4;
    cudaFuncSetAttribute(attn_h16,
                         cudaFuncAttributeMaxDynamicSharedMemorySize, ASM);

    prep_convert<<<8704 + 64, 256>>>(utt, rc, summ, mem,
                                     (const unsigned char*)mask_raw, lengths);
    {
        int pack_blocks = (QL * NWORD * 32 + 255) / 256;   // 9248
        wconv_pack<<<1024 + pack_blocks, 256>>>(w_q, w_kv, w_out,
                                                mask_raw, lengths);
    }
    qkv_gemm<<<dim3(12, 68), 256, GSM>>>(qin16, kvin16, wqt, wkvt, b_q, b_kv);
    // persistent attention: 296 CTAs (2/SM on 148 SMs), work-stealing
    attn_h16<<<296, 256, ASM>>>(lengths);
    out_gemm<<<dim3(4, 68), 256, GSM>>>(attn16, wot, b_out, out);
}

// round 13
// speedup vs baseline: 1.0514x; 1.0514x over previous
#include <cuda_runtime.h>
#include <cuda_fp16.h>
#include <cstdint>

#define UQ   2048
#define BB   4
#define DD   512
#define QL   2176
#define KVL  2176
#define NH   8
#define DH   64
#define NEGINF (-100000000.0f)
#define MROWS (QL*BB)          // 8704
#define RCU_ROWS 2112
#define RCU_SZ (2112*4*512)
#define NWORD 34               // KVL/64
#define QSCALE (0.125f * 1.44269504088896f)   // dh^-0.5 * log2(e)

// -------------------- device scratch ----------------------------------------
__device__ __half g_qin16 [MROWS * DD];
__device__ __half g_kvin16[MROWS * DD];
__device__ __half g_q16   [MROWS * DD];
__device__ __half g_k16   [MROWS * DD];
__device__ __half g_v16   [MROWS * DD];   // plain [token*BB+b][dh] (same as K)
__device__ __half g_attn16[MROWS * DD];
__device__ __half g_wqt [512 * 512];
__device__ __half g_wkvt[1024 * 512];
__device__ __half g_wot [512 * 512];
__device__ unsigned long long g_mbits[BB * QL * NWORD];
__device__ int g_flags[3];    // static-zero; monotone atomicOr (replay-stable)
__device__ int g_perm[BB];    // batches sorted by length desc (LPT)

// -------------------- helpers ------------------------------------------------
__device__ __forceinline__ void hmma(float* c,
    uint32_t a0, uint32_t a1, uint32_t a2, uint32_t a3,
    uint32_t b0, uint32_t b1) {
    asm volatile(
        "mma.sync.aligned.m16n8k16.row.col.f32.f16.f16.f32 "
        "{%0,%1,%2,%3}, {%4,%5,%6,%7}, {%8,%9}, {%0,%1,%2,%3};\n"
        : "+f"(c[0]), "+f"(c[1]), "+f"(c[2]), "+f"(c[3])
        : "r"(a0), "r"(a1), "r"(a2), "r"(a3), "r"(b0), "r"(b1));
}
__device__ __forceinline__ void ldsm4(uint32_t& r0, uint32_t& r1,
                                      uint32_t& r2, uint32_t& r3, uint32_t a) {
    asm volatile("ldmatrix.sync.aligned.m8n8.x4.shared.b16 {%0,%1,%2,%3}, [%4];"
        : "=r"(r0), "=r"(r1), "=r"(r2), "=r"(r3) : "r"(a));
}
__device__ __forceinline__ void ldsm4t(uint32_t& r0, uint32_t& r1,
                                       uint32_t& r2, uint32_t& r3, uint32_t a) {
    asm volatile("ldmatrix.sync.aligned.m8n8.x4.trans.shared.b16 {%0,%1,%2,%3}, [%4];"
        : "=r"(r0), "=r"(r1), "=r"(r2), "=r"(r3) : "r"(a));
}
__device__ __forceinline__ uint32_t packh2(float lo, float hi) {
    uint32_t r; asm("cvt.rn.f16x2.f32 %0, %1, %2;" : "=r"(r) : "f"(hi), "f"(lo));
    return r;
}
__device__ __forceinline__ float ex2(float x) {
    float r; asm("ex2.approx.f32 %0, %1;" : "=f"(r) : "f"(x)); return r;
}
__device__ __forceinline__ uint32_t s2u(const void* p) {
    return (uint32_t)__cvta_generic_to_shared(p);
}
#define CP16(dst, src) \
    asm volatile("cp.async.cg.shared.global [%0], [%1], 16;\n" :: "r"(dst), "l"(src))
#define CP_COMMIT() asm volatile("cp.async.commit_group;\n")

// -------------------- fused prep: gather/convert + mask sniff + LPT perm -----
__global__ void prep_convert(const float* __restrict__ utt,
                             const float* __restrict__ rc,
                             const float* __restrict__ summ,
                             const float* __restrict__ mem,
                             const unsigned char* __restrict__ rawmask,
                             const int* __restrict__ lengths) {
    const int QN = MROWS * 128;
    int bid = blockIdx.x;
    if (bid < 8704) {
        int i = bid * blockDim.x + threadIdx.x;
        if (i < QN) {
            int row = i >> 7;
            float4 v;
            if (row < 256)       v = ((const float4*)rc)[i];
            else if (row < 8448) v = ((const float4*)utt)[i - 256 * 128];
            else                 v = ((const float4*)summ)[i - 8448 * 128];
            uint2 o; o.x = packh2(v.x, v.y); o.y = packh2(v.z, v.w);
            ((uint2*)g_qin16)[i] = o;
        } else {
            int j = i - QN;
            int row = j >> 7;
            float4 v;
            if (row < 256)      v = ((const float4*)mem)[j];
            else if (row < 512) v = ((const float4*)rc)[j - 256 * 128];
            else                v = ((const float4*)utt)[j - 512 * 128];
            uint2 o; o.x = packh2(v.x, v.y); o.y = packh2(v.z, v.w);
            ((uint2*)g_kvin16)[j] = o;
        }
    } else {
        int sb = bid - 8704;
        int f0 = 0, f1 = 0, f2 = 0;
        const int SCAN = 1 << 20;
        int stride = 64 * blockDim.x * 4;
        for (int i = (sb * blockDim.x + threadIdx.x) * 4; i < SCAN; i += stride) {
            uchar4 v = *(const uchar4*)(rawmask + i);
            if (v.x > 1 || v.y > 1) f0 = 1;
            if (v.z > 1 || v.w > 1) f1 = 1;
            if (v.y | v.z | v.w)    f2 = 1;
        }
        if (f0) atomicOr(&g_flags[0], 1);
        if (f1) atomicOr(&g_flags[1], 1);
        if (f2) atomicOr(&g_flags[2], 1);
        if (sb == 0 && threadIdx.x == 0) {
            int len[BB], idx[BB];
            for (int i = 0; i < BB; i++) { len[i] = __ldg(lengths + i); idx[i] = i; }
            for (int i = 1; i < BB; i++) {
                int l = len[i], ix = idx[i], j = i - 1;
                while (j >= 0 && len[j] < l) {
                    len[j + 1] = len[j]; idx[j + 1] = idx[j]; j--;
                }
                len[j + 1] = l; idx[j + 1] = ix;
            }
            for (int i = 0; i < BB; i++) g_perm[i] = idx[i];
        }
    }
}

// -------------------- fused weight transpose + mask pack ----------------------
__global__ void wconv_pack(const float* __restrict__ wq,
                           const float* __restrict__ wkv,
                           const float* __restrict__ wo,
                           const void* __restrict__ raw,
                           const int* __restrict__ lengths) {
    int bid = blockIdx.x;
    if (bid < 1024) {
        __shared__ float tile[32][33];
        const float* W; __half* Wt; int NN, bx, by;
        if (bid < 256)      { W = wq;  Wt = g_wqt;  NN = 512;  bx = bid & 15; by = bid >> 4; }
        else if (bid < 768) { int b2 = bid - 256; W = wkv; Wt = g_wkvt; NN = 1024; bx = b2 & 31; by = b2 >> 5; }
        else                { int b2 = bid - 768; W = wo;  Wt = g_wot;  NN = 512;  bx = b2 & 15; by = b2 >> 4; }
        int x = threadIdx.x & 31, y0 = threadIdx.x >> 5;
        #pragma unroll
        for (int yy = y0; yy < 32; yy += 8)
            tile[yy][x] = W[(size_t)(by * 32 + yy) * NN + bx * 32 + x];
        __syncthreads();
        #pragma unroll
        for (int yy = y0; yy < 32; yy += 8)
            Wt[(size_t)(bx * 32 + yy) * 512 + by * 32 + x] =
                __float2half_rn(tile[x][yy]);
        return;
    }
    // ---- mask pack: one warp per (q, word) ----
    int warp = ((bid - 1024) * blockDim.x + threadIdx.x) >> 5;
    int lane = threadIdx.x & 31;
    if (warp >= QL * NWORD) return;
    int q = warp / NWORD, w = warp - q * NWORD;

    int kind;
    if (g_flags[0])      kind = 3;
    else if (g_flags[1]) kind = 2;
    else if (g_flags[2]) kind = 0;
    else                 kind = 1;

    size_t base = (size_t)q * KVL + w * 64;
    bool m0, m1;
    if (kind == 0) {
        const unsigned char* p = (const unsigned char*)raw;
        m0 = p[base + lane] != 0; m1 = p[base + 32 + lane] != 0;
    } else if (kind == 1) {
        const int* p = (const int*)raw;
        m0 = p[base + lane] != 0; m1 = p[base + 32 + lane] != 0;
    } else if (kind == 2) {
        const float* p = (const float*)raw;
        m0 = p[base + lane] != 0.f; m1 = p[base + 32 + lane] != 0.f;
    } else {
        const unsigned short* p = (const unsigned short*)raw;
        m0 = (p[base + lane] & 0x7fff) != 0;
        m1 = (p[base + 32 + lane] & 0x7fff) != 0;
    }
    uint32_t lo = __ballot_sync(0xffffffffu, m0);
    uint32_t hi = __ballot_sync(0xffffffffu, m1);
    unsigned long long word = (unsigned long long)lo |
                              ((unsigned long long)hi << 32);
    if (lane < 4) {
        int limit = 128 + __ldg(lengths + lane);
        int k0 = w * 64;
        unsigned long long pad;
        if (limit <= k0)           pad = ~0ull;
        else if (limit >= k0 + 64) pad = 0ull;
        else                       pad = (~0ull) << (limit - k0);
        g_mbits[((size_t)lane * QL + q) * NWORD + w] = word | pad;
    }
}

// -------------------- fp16 GEMM core (ldmatrix fragments) --------------------
struct GemmAcc { float a[2][8][4]; };

__device__ __forceinline__ void gemm_main(uint32_t* sm, const __half* A,
                                          const __half* Wt, int m0, int n0,
                                          GemmAcc& acc) {
    const int tid = threadIdx.x;
    const int wid = tid >> 5, lane = tid & 31;
    const int qq = lane >> 3, rr = lane & 7;
    const int wm = wid & 3, wn = wid >> 2;

    const uint32_t a_off = (uint32_t)((((qq & 1) << 3) + rr) * 36 + ((qq >> 1) << 2));
    const uint32_t b_off = (uint32_t)(((wn * 64) + ((qq >> 1) << 3) + rr) * 36 + ((qq & 1) << 2));

    #pragma unroll
    for (int mf = 0; mf < 2; mf++)
        #pragma unroll
        for (int nf = 0; nf < 8; nf++)
            #pragma unroll
            for (int e = 0; e < 4; e++) acc.a[mf][nf][e] = 0.f;

    auto issue = [&](int t) {
        int k0 = t * 64;
        uint32_t* As = sm + (t & 1) * 4608;
        uint32_t* Bs = sm + 9216 + (t & 1) * 4608;
        #pragma unroll
        for (int l = 0; l < 4; l++) {
            int item = tid + l * 256;
            int row = item >> 3, c = item & 7;
            CP16(s2u(As + row * 36 + c * 4),
                 A + (size_t)(m0 + row) * 512 + k0 + c * 8);
        }
        #pragma unroll
        for (int l = 0; l < 4; l++) {
            int item = tid + l * 256;
            int row = item >> 3, c = item & 7;
            CP16(s2u(Bs + row * 36 + c * 4),
                 Wt + (size_t)(n0 + row) * 512 + k0 + c * 8);
        }
        CP_COMMIT();
    };

    issue(0);
    #pragma unroll 1
    for (int t = 0; t < 8; t++) {
        if (t + 1 < 8) {
            issue(t + 1);
            asm volatile("cp.async.wait_group 1;\n");
        } else {
            asm volatile("cp.async.wait_group 0;\n");
        }
        __syncthreads();
        uint32_t as_base = s2u(sm + (t & 1) * 4608) + a_off * 4;
        uint32_t bs_base = s2u(sm + 9216 + (t & 1) * 4608) + b_off * 4;
        #pragma unroll
        for (int kc = 0; kc < 4; kc++) {
            uint32_t a[2][4];
            #pragma unroll
            for (int mf = 0; mf < 2; mf++)
                ldsm4(a[mf][0], a[mf][1], a[mf][2], a[mf][3],
                      as_base + (uint32_t)(((wm * 32 + mf * 16) * 36 + kc * 8) * 4));
            #pragma unroll
            for (int P = 0; P < 4; P++) {
                uint32_t b0, b1, b2, b3;
                ldsm4(b0, b1, b2, b3,
                      bs_base + (uint32_t)((P * 16 * 36 + kc * 8) * 4));
                hmma(acc.a[0][2 * P],     a[0][0], a[0][1], a[0][2], a[0][3], b0, b1);
                hmma(acc.a[1][2 * P],     a[1][0], a[1][1], a[1][2], a[1][3], b0, b1);
                hmma(acc.a[0][2 * P + 1], a[0][0], a[0][1], a[0][2], a[0][3], b2, b3);
                hmma(acc.a[1][2 * P + 1], a[1][0], a[1][1], a[1][2], a[1][3], b2, b3);
            }
        }
        __syncthreads();
    }
}

// -------------------- merged Q + KV projection -------------------------------
__global__ __launch_bounds__(256, 2)
void qkv_gemm(const __half* __restrict__ qA, const __half* __restrict__ kvA,
              const __half* __restrict__ wq, const __half* __restrict__ wkv,
              const float* __restrict__ bq, const float* __restrict__ bkv) {
    extern __shared__ uint32_t sm[];
    const bool isQ = blockIdx.x < 4;
    const int n0 = isQ ? blockIdx.x * 128 : (blockIdx.x - 4) * 128;
    const int m0 = blockIdx.y * 128;
    const __half* A  = isQ ? qA : kvA;
    const __half* Wt = isQ ? wq : wkv;
    const float* bias = isQ ? bq : bkv;

    GemmAcc acc;
    gemm_main(sm, A, Wt, m0, n0, acc);

    const int lane = threadIdx.x & 31, wid = threadIdx.x >> 5;
    const int g = lane >> 2, tig = lane & 3;
    const int wm = wid & 3, wn = wid >> 2;
    #pragma unroll
    for (int mf = 0; mf < 2; mf++) {
        int row0 = m0 + wm * 32 + mf * 16 + g;
        int row1 = row0 + 8;
        #pragma unroll
        for (int nf = 0; nf < 8; nf++) {
            int col = n0 + wn * 64 + nf * 8 + 2 * tig;
            float bi0 = __ldg(bias + col), bi1 = __ldg(bias + col + 1);
            float v00 = acc.a[mf][nf][0] + bi0, v01 = acc.a[mf][nf][1] + bi1;
            float v10 = acc.a[mf][nf][2] + bi0, v11 = acc.a[mf][nf][3] + bi1;
            if (isQ) {
                *(__half2*)(&g_q16[(size_t)row0 * DD + col]) =
                    __floats2half2_rn(v00 * QSCALE, v01 * QSCALE);
                *(__half2*)(&g_q16[(size_t)row1 * DD + col]) =
                    __floats2half2_rn(v10 * QSCALE, v11 * QSCALE);
            } else {
                __half* dst = (col < 512) ? g_k16 : g_v16;
                int c = (col < 512) ? col : col - 512;
                *(__half2*)(&dst[(size_t)row0 * DD + c]) = __floats2half2_rn(v00, v01);
                *(__half2*)(&dst[(size_t)row1 * DD + c]) = __floats2half2_rn(v10, v11);
            }
        }
    }
}

// -------------------- output projection (slice/clip scatter) -----------------
__global__ __launch_bounds__(256, 2)
void out_gemm(const __half* __restrict__ A, const __half* __restrict__ Wt,
              const float* __restrict__ bias, float* __restrict__ C) {
    extern __shared__ uint32_t sm[];
    const int m0 = blockIdx.y * 128, n0 = blockIdx.x * 128;
    GemmAcc acc;
    gemm_main(sm, A, Wt, m0, n0, acc);

    const int lane = threadIdx.x & 31, wid = threadIdx.x >> 5;
    const int g = lane >> 2, tig = lane & 3;
    const int wm = wid & 3, wn = wid >> 2;
    #pragma unroll
    for (int mf = 0; mf < 2; mf++) {
        int row0 = m0 + wm * 32 + mf * 16 + g;
        #pragma unroll
        for (int nf = 0; nf < 8; nf++) {
            int col = n0 + wn * 64 + nf * 8 + 2 * tig;
            float bi0 = __ldg(bias + col), bi1 = __ldg(bias + col + 1);
            float vs[2][2] = {
                {acc.a[mf][nf][0] + bi0, acc.a[mf][nf][1] + bi1},
                {acc.a[mf][nf][2] + bi0, acc.a[mf][nf][3] + bi1}};
            #pragma unroll
            for (int r = 0; r < 2; r++) {
                int m = row0 + r * 8;
                int q = m >> 2, b = m & 3;
                if (q < RCU_ROWS) {
                    *(float2*)(C + (size_t)m * DD + col) =
                        make_float2(vs[r][0], vs[r][1]);
                } else if (q < QL - 1) {
                    float a0 = fminf(fmaxf(vs[r][0], -10.f), 10.f);
                    float a1 = fminf(fmaxf(vs[r][1], -10.f), 10.f);
                    *(float2*)(C + RCU_SZ +
                        (size_t)((q - RCU_ROWS) * BB + b) * DD + col) =
                        make_float2(a0, a1);
                }
            }
        }
    }
}

// -------------------- fp16 flash attention (max-free, l via ones-mma) ---------
__global__ __launch_bounds__(256)
void attn_h16(const int* __restrict__ lengths) {
    extern __shared__ uint32_t sm[];
    uint32_t* Qs = sm;

    const int tid = threadIdx.x;
    const int wid = tid >> 5, lane = tid & 31;
    const int g = lane >> 2, tig = lane & 3;
    const int qq = lane >> 3, rr = lane & 7;
    const int b = g_perm[blockIdx.y >> 3];
    const int h = blockIdx.y & 7;
    const int q0 = blockIdx.x * 128;
    const int wrow = wid * 16;
    const int qg0 = q0 + wrow + g;
    const int qg1 = qg0 + 8;
    const unsigned long long* mrow0 = g_mbits + ((size_t)b * QL + qg0) * NWORD;
    const unsigned long long* mrow1 = g_mbits + ((size_t)b * QL + qg1) * NWORD;

    const int limit = 128 + __ldg(lengths + b);
    const int NTb = min(NWORD, (limit + 63) >> 6);

    const uint32_t qa_off = (uint32_t)((wrow + ((qq & 1) << 3) + rr) * 36 + ((qq >> 1) << 2));
    const uint32_t kb_off = (uint32_t)((((qq >> 1) << 3) + rr) * 36 + ((qq & 1) << 2));
    const uint32_t vb_off = (uint32_t)((((qq & 1) << 3) + rr) * 36 + ((qq >> 1) << 2));

    auto load_kv = [&](int t, uint32_t* stage) {
        int k0 = t * 64;
        uint32_t* Ks = stage;
        uint32_t* Vs = stage + 2304;
        #pragma unroll
        for (int l = 0; l < 2; l++) {
            int item = tid + l * 256;
            int row = item >> 3, c = item & 7;
            CP16(s2u(Ks + row * 36 + c * 4),
                 g_k16 + ((size_t)(k0 + row) * BB + b) * DD + h * DH + c * 8);
        }
        #pragma unroll
        for (int l = 0; l < 2; l++) {
            int item = tid + l * 256;
            int row = item >> 3, c = item & 7;
            CP16(s2u(Vs + row * 36 + c * 4),
                 g_v16 + ((size_t)(k0 + row) * BB + b) * DD + h * DH + c * 8);
        }
    };

    #pragma unroll
    for (int l = 0; l < 4; l++) {
        int item = tid + l * 256;
        int row = item >> 3, c = item & 7;
        CP16(s2u(Qs + row * 36 + c * 4),
             g_q16 + ((size_t)(q0 + row) * BB + b) * DD + h * DH + c * 8);
    }
    load_kv(0, sm + 4608);
    CP_COMMIT();
    if (1 < NTb) load_kv(1, sm + 4608 + 4608);
    CP_COMMIT();

    float o[8][4];
    #pragma unroll
    for (int nf = 0; nf < 8; nf++)
        #pragma unroll
        for (int e = 0; e < 4; e++) o[nf][e] = 0.f;
    float ol[4] = {0.f, 0.f, 0.f, 0.f};   // row-sum accumulator (ones-mma)
    const uint32_t ONES = 0x3C003C00u;    // fp16 1.0 x2

    // precompute loop-invariant Q ldmatrix addresses
    uint32_t qa_addr[4];
    {
        uint32_t base = s2u(Qs) + qa_off * 4;
        #pragma unroll
        for (int kc = 0; kc < 4; kc++) qa_addr[kc] = base + (uint32_t)(kc * 32);
    }

    int st = 0, st2 = 2;
    #pragma unroll 1
    for (int t = 0; t < NTb; t++) {
        unsigned long long w0 = mrow0[t], w1 = mrow1[t];

        if (t + 2 < NTb) load_kv(t + 2, sm + 4608 + st2 * 4608);
        CP_COMMIT();
        asm volatile("cp.async.wait_group 2;\n");
        __syncthreads();

        uint32_t* stage = sm + 4608 + st * 4608;
        const uint32_t ks_base = s2u(stage) + kb_off * 4;
        const uint32_t vs_base = s2u(stage + 2304) + vb_off * 4;

        // S = Q @ K^T
        float s[8][4];
        #pragma unroll
        for (int nf = 0; nf < 8; nf++)
            #pragma unroll
            for (int e = 0; e < 4; e++) s[nf][e] = 0.f;
        #pragma unroll
        for (int kc = 0; kc < 4; kc++) {
            uint32_t a0, a1, a2, a3;
            ldsm4(a0, a1, a2, a3, qa_addr[kc]);
            #pragma unroll
            for (int P = 0; P < 4; P++) {
                uint32_t b0, b1, b2, b3;
                ldsm4(b0, b1, b2, b3,
                      ks_base + (uint32_t)((P * 16 * 36 + kc * 8) * 4));
                hmma(s[2 * P],     a0, a1, a2, a3, b0, b1);
                hmma(s[2 * P + 1], a0, a1, a2, a3, b2, b3);
            }
        }

        // mask -> p = 2^s  (no max, no scalar l accumulation)
        #pragma unroll
        for (int nf = 0; nf < 8; nf++) {
            int sh = nf * 8 + 2 * tig;
            uint32_t b0 = (uint32_t)(w0 >> sh);
            uint32_t b1 = (uint32_t)(w1 >> sh);
            if (b0 & 1) s[nf][0] = NEGINF;
            if (b0 & 2) s[nf][1] = NEGINF;
            if (b1 & 1) s[nf][2] = NEGINF;
            if (b1 & 2) s[nf][3] = NEGINF;
            s[nf][0] = ex2(s[nf][0]);
            s[nf][1] = ex2(s[nf][1]);
            s[nf][2] = ex2(s[nf][2]);
            s[nf][3] = ex2(s[nf][3]);
        }

        // O += P @ V ; l += P @ 1 (ones-mma: every column = row sum)
        #pragma unroll
        for (int kc = 0; kc < 4; kc++) {
            uint32_t pa0 = packh2(s[2 * kc][0],     s[2 * kc][1]);
            uint32_t pa1 = packh2(s[2 * kc][2],     s[2 * kc][3]);
            uint32_t pa2 = packh2(s[2 * kc + 1][0], s[2 * kc + 1][1]);
            uint32_t pa3 = packh2(s[2 * kc + 1][2], s[2 * kc + 1][3]);
            #pragma unroll
            for (int P = 0; P < 4; P++) {
                uint32_t b0, b1, b2, b3;
                ldsm4t(b0, b1, b2, b3,
                       vs_base + (uint32_t)((kc * 16 * 36 + P * 8) * 4));
                hmma(o[2 * P],     pa0, pa1, pa2, pa3, b0, b1);
                hmma(o[2 * P + 1], pa0, pa1, pa2, pa3, b2, b3);
            }
            hmma(ol, pa0, pa1, pa2, pa3, ONES, ONES);
        }
        __syncthreads();

        st  = (st  == 2) ? 0 : st + 1;
        st2 = (st2 == 2) ? 0 : st2 + 1;
    }

    // ol[0] = row qg0 sum, ol[2] = row qg1 sum (all columns equal)
    float inv0 = 1.0f / ol[0], inv1 = 1.0f / ol[2];
    #pragma unroll
    for (int nf = 0; nf < 8; nf++) {
        int col = h * DH + nf * 8 + 2 * tig;
        *(__half2*)(&g_attn16[((size_t)qg0 * BB + b) * DD + col]) =
            __floats2half2_rn(o[nf][0] * inv0, o[nf][1] * inv0);
        *(__half2*)(&g_attn16[((size_t)qg1 * BB + b) * DD + col]) =
            __floats2half2_rn(o[nf][2] * inv1, o[nf][3] * inv1);
    }
}

// -------------------- launch ------------------------------------------------
extern "C" void kernel_launch(void* const* d_in, const int* in_sizes, int n_in,
                              void* d_out, int out_size) {
    const float* utt      = (const float*)d_in[0];
    const int*   lengths  = (const int*)d_in[1];
    const float* rc       = (const float*)d_in[2];
    const float* summ     = (const float*)d_in[3];
    const float* mem      = (const float*)d_in[4];
    const void*  mask_raw = (const void*)d_in[5];
    const float* w_q   = (const float*)d_in[6];
    const float* b_q   = (const float*)d_in[7];
    const float* w_kv  = (const float*)d_in[8];
    const float* b_kv  = (const float*)d_in[9];
    const float* w_out = (const float*)d_in[10];
    const float* b_out = (const float*)d_in[11];
    float* out = (float*)d_out;

    void *p;
    cudaGetSymbolAddress(&p, g_qin16);  __half* qin16  = (__half*)p;
    cudaGetSymbolAddress(&p, g_kvin16); __half* kvin16 = (__half*)p;
    cudaGetSymbolAddress(&p, g_attn16); __half* attn16 = (__half*)p;
    cudaGetSymbolAddress(&p, g_wqt);    __half* wqt    = (__half*)p;
    cudaGetSymbolAddress(&p, g_wkvt);   __half* wkvt   = (__half*)p;
    cudaGetSymbolAddress(&p, g_wot);    __half* wot    = (__half*)p;

    const int GSM = 18432 * 4;
    cudaFuncSetAttribute(qkv_gemm,
                         cudaFuncAttributeMaxDynamicSharedMemorySize, GSM);
    cudaFuncSetAttribute(out_gemm,
                         cudaFuncAttributeMaxDynamicSharedMemorySize, GSM);
    const int ASM = 18432 * 4;
    cudaFuncSetAttribute(attn_h16,
                         cudaFuncAttributeMaxDynamicSharedMemorySize, ASM);

    prep_convert<<<8704 + 64, 256>>>(utt, rc, summ, mem,
                                     (const unsigned char*)mask_raw, lengths);
    {
        int pack_blocks = (QL * NWORD * 32 + 255) / 256;   // 9248
        wconv_pack<<<1024 + pack_blocks, 256>>>(w_q, w_kv, w_out,
                                                mask_raw, lengths);
    }
    qkv_gemm<<<dim3(12, 68), 256, GSM>>>(qin16, kvin16, wqt, wkvt, b_q, b_kv);
    attn_h16<<<dim3(QL / 128, BB * NH), 256, ASM>>>(lengths);
    out_gemm<<<dim3(4, 68), 256, GSM>>>(attn16, wot, b_out, out);
}